// round 1
// baseline (speedup 1.0000x reference)
#include <cuda_runtime.h>
#include <math.h>
#include <cstdint>

// ---------------------------------------------------------------------------
// Problem constants (fixed shapes)
// ---------------------------------------------------------------------------
namespace {
constexpr int B  = 4;
constexpr int C  = 256;
constexpr int H  = 128;
constexpr int W  = 128;
constexpr int HW = H * W;          // 16384
constexpr int NC = 19;
constexpr int NH = 8;
constexpr int HD = 32;
constexpr int C4 = 4 * C;          // 1024
constexpr float SCALE = 0.17677669529663687f;  // 32^-0.5
constexpr float EPS = 1e-5f;
}

// ---------------------------------------------------------------------------
// Scratch (static __device__ arrays; no allocation allowed)
// ---------------------------------------------------------------------------
__device__ float g_query[B * C * HW];
__device__ float g_fused[B * C * HW];
__device__ float g_mask [B * NC * HW];
__device__ float g_xa   [B * C * HW];
__device__ float g_weff [NC * C];
__device__ float g_cf   [B * NC * C];
__device__ float g_kbuf [B * NC * C];
__device__ float g_vbuf [B * NC * C];
__device__ float g_qd   [B * C * HW];
__device__ float g_qq   [B * C * HW];
__device__ float g_att  [B * C * HW];
__device__ float g_outb [B * C * HW];
__device__ float g_y    [B * C * HW];
__device__ float g_hid  [B * C4 * HW];   // 256 MB
__device__ float g_hid2 [B * C4 * HW];   // 256 MB

// ---------------------------------------------------------------------------
// K1: LN(low) -> query ; LN(high) ; fused = 0.5*(query + ln_high)
// thread per (b, spatial) position; channel loop coalesced across threads.
// ---------------------------------------------------------------------------
__global__ void ln_fuse_kernel(const float* __restrict__ low, const float* __restrict__ high,
                               const float* __restrict__ gl, const float* __restrict__ bl,
                               const float* __restrict__ gh, const float* __restrict__ bh)
{
    int pos = blockIdx.x * blockDim.x + threadIdx.x;
    if (pos >= B * HW) return;
    int b = pos / HW, l = pos % HW;
    const float* lp = low  + (size_t)b * C * HW + l;
    const float* hp = high + (size_t)b * C * HW + l;
    float s1 = 0.f, s2 = 0.f, t1 = 0.f, t2 = 0.f;
    #pragma unroll 8
    for (int c = 0; c < C; c++) {
        float a = lp[(size_t)c * HW]; s1 += a; s2 += a * a;
        float e = hp[(size_t)c * HW]; t1 += e; t2 += e * e;
    }
    float mu1 = s1 * (1.f / C), mu2 = t1 * (1.f / C);
    float i1 = rsqrtf(s2 * (1.f / C) - mu1 * mu1 + EPS);
    float i2 = rsqrtf(t2 * (1.f / C) - mu2 * mu2 + EPS);
    float* qo = g_query + (size_t)b * C * HW + l;
    float* fo = g_fused + (size_t)b * C * HW + l;
    #pragma unroll 8
    for (int c = 0; c < C; c++) {
        float q = (lp[(size_t)c * HW] - mu1) * i1 * gl[c] + bl[c];
        float k = (hp[(size_t)c * HW] - mu2) * i2 * gh[c] + bh[c];
        qo[(size_t)c * HW] = q;
        fo[(size_t)c * HW] = 0.5f * (q + k);
    }
}

// ---------------------------------------------------------------------------
// LN over channels (generic single-tensor)
// ---------------------------------------------------------------------------
__global__ void ln_kernel(const float* __restrict__ in, float* __restrict__ out,
                          const float* __restrict__ g, const float* __restrict__ bb)
{
    int pos = blockIdx.x * blockDim.x + threadIdx.x;
    if (pos >= B * HW) return;
    int b = pos / HW, l = pos % HW;
    const float* ip = in + (size_t)b * C * HW + l;
    float s1 = 0.f, s2 = 0.f;
    #pragma unroll 8
    for (int c = 0; c < C; c++) { float a = ip[(size_t)c * HW]; s1 += a; s2 += a * a; }
    float mu = s1 * (1.f / C);
    float iv = rsqrtf(s2 * (1.f / C) - mu * mu + EPS);
    float* op = out + (size_t)b * C * HW + l;
    #pragma unroll 8
    for (int c = 0; c < C; c++)
        op[(size_t)c * HW] = (ip[(size_t)c * HW] - mu) * iv * g[c] + bb[c];
}

// ---------------------------------------------------------------------------
// K2: compose mask-path weights: W_eff[n][ci] = sum_j ml2[n, g*64+j] * ml1[(g*64+j), ci%64]
// ---------------------------------------------------------------------------
__global__ void weff_kernel(const float* __restrict__ w_ml2, const float* __restrict__ w_ml1)
{
    int n = blockIdx.x, ci = threadIdx.x;
    int g = ci >> 6, jj = ci & 63;
    float acc = 0.f;
    #pragma unroll
    for (int j = 0; j < 64; j++) {
        int m = g * 64 + j;
        acc += w_ml2[n * C + m] * w_ml1[m * 64 + jj];
    }
    g_weff[n * C + ci] = acc;
}

// ---------------------------------------------------------------------------
// K3: mask logits [B,NC,HW] and xa (grouped 1x1 conv) [B,C,HW] from fused.
// One thread per spatial position; per-group register tile of 64 fused vals.
// ---------------------------------------------------------------------------
__global__ void mask_xa_kernel(const float* __restrict__ w_align)
{
    extern __shared__ float sm[];
    float* weff_s = sm;                 // NC*C floats
    float* wal_s  = sm + NC * C;        // C*64 floats
    int tid = threadIdx.x;
    for (int i = tid; i < NC * C; i += 128) weff_s[i] = g_weff[i];
    for (int i = tid; i < C * 64; i += 128) wal_s[i] = w_align[i];
    __syncthreads();
    int b = blockIdx.y;
    int l = blockIdx.x * 128 + tid;
    const float* fp = g_fused + (size_t)b * C * HW + l;
    float macc[NC];
    #pragma unroll
    for (int n = 0; n < NC; n++) macc[n] = 0.f;
    for (int g = 0; g < 4; g++) {
        float fv[64];
        #pragma unroll
        for (int j = 0; j < 64; j++) fv[j] = fp[(size_t)(g * 64 + j) * HW];
        for (int n = 0; n < NC; n++) {
            float a = 0.f;
            #pragma unroll
            for (int j = 0; j < 64; j++) a += weff_s[n * C + g * 64 + j] * fv[j];
            macc[n] += a;
        }
        for (int co = 0; co < 64; co++) {
            float a = 0.f;
            #pragma unroll
            for (int j = 0; j < 64; j++) a += wal_s[(g * 64 + co) * 64 + j] * fv[j];
            g_xa[(size_t)b * C * HW + (size_t)(g * 64 + co) * HW + l] = a;
        }
    }
    #pragma unroll
    for (int n = 0; n < NC; n++)
        g_mask[(size_t)b * NC * HW + (size_t)n * HW + l] = macc[n];
}

// ---------------------------------------------------------------------------
// K4: spatial softmax over HW for each (b, nc) row of mask (in place)
// ---------------------------------------------------------------------------
__global__ void softmax_hw_kernel()
{
    __shared__ float red[256];
    int row = blockIdx.x;                 // b*NC + n
    float* p = g_mask + (size_t)row * HW;
    int tid = threadIdx.x;
    float m = -1e30f;
    for (int i = tid; i < HW; i += 256) m = fmaxf(m, p[i]);
    red[tid] = m; __syncthreads();
    for (int s = 128; s > 0; s >>= 1) { if (tid < s) red[tid] = fmaxf(red[tid], red[tid + s]); __syncthreads(); }
    m = red[0]; __syncthreads();
    float s = 0.f;
    for (int i = tid; i < HW; i += 256) s += expf(p[i] - m);
    red[tid] = s; __syncthreads();
    for (int st = 128; st > 0; st >>= 1) { if (tid < st) red[tid] += red[tid + st]; __syncthreads(); }
    float inv = 1.f / red[0];
    for (int i = tid; i < HW; i += 256) p[i] = expf(p[i] - m) * inv;
}

// ---------------------------------------------------------------------------
// K5: cf[b,n,c] = sum_l mask[b,n,l] * xa[b,c,l]   (K=16384 reduction)
// Block per (b,c); thread-strided over l; 19 accumulators.
// ---------------------------------------------------------------------------
__global__ void cf_kernel()
{
    int c = blockIdx.x, b = blockIdx.y;
    int tid = threadIdx.x;
    const float* xp = g_xa + (size_t)(b * C + c) * HW;
    const float* mp = g_mask + (size_t)b * NC * HW;
    float acc[NC];
    #pragma unroll
    for (int n = 0; n < NC; n++) acc[n] = 0.f;
    for (int l = tid; l < HW; l += 256) {
        float x = xp[l];
        #pragma unroll
        for (int n = 0; n < NC; n++) acc[n] += x * mp[(size_t)n * HW + l];
    }
    __shared__ float red[256];
    for (int n = 0; n < NC; n++) {
        red[tid] = acc[n]; __syncthreads();
        for (int s = 128; s > 0; s >>= 1) { if (tid < s) red[tid] += red[tid + s]; __syncthreads(); }
        if (tid == 0) g_cf[((size_t)b * NC + n) * C + c] = red[0];
        __syncthreads();
    }
}

// ---------------------------------------------------------------------------
// K6: cf memory-mix + kv = cf @ w_kv^T + b_kv ; split into k/v buffers
// ---------------------------------------------------------------------------
__global__ void kv_kernel(const float* __restrict__ w_kv, const float* __restrict__ b_kv,
                          const float* __restrict__ memory)
{
    int row = blockIdx.x;               // b*NC + n
    int n = row % NC;
    int tid = threadIdx.x;              // 512
    __shared__ float cfs[C];
    if (tid < C) cfs[tid] = 0.9f * g_cf[(size_t)row * C + tid] + 0.1f * memory[n * C + tid];
    __syncthreads();
    float acc = b_kv[tid];
    #pragma unroll 8
    for (int c = 0; c < C; c++) acc += cfs[c] * w_kv[(size_t)tid * C + c];
    if (tid < C) g_kbuf[(size_t)row * C + tid] = acc;
    else         g_vbuf[(size_t)row * C + tid - C] = acc;
}

// ---------------------------------------------------------------------------
// Depthwise 3x3 conv (+bias) with optional exact GELU epilogue
// ---------------------------------------------------------------------------
__global__ void dw3x3_kernel(const float* __restrict__ in, float* __restrict__ out,
                             const float* __restrict__ w, const float* __restrict__ bias,
                             int Cn, int doGelu)
{
    long long idx = (long long)blockIdx.x * 256 + threadIdx.x;
    int x = (int)(idx % W);
    int y = (int)((idx / W) % H);
    long long bc = idx / HW;
    int c = (int)(bc % Cn);
    const float* ip = in + (size_t)bc * HW;
    const float* wp = w + c * 9;
    float acc = bias[c];
    #pragma unroll
    for (int dy = -1; dy <= 1; dy++) {
        int yy = y + dy;
        if (yy < 0 || yy >= H) continue;
        #pragma unroll
        for (int dx = -1; dx <= 1; dx++) {
            int xx = x + dx;
            if (xx < 0 || xx >= W) continue;
            acc += ip[yy * W + xx] * wp[(dy + 1) * 3 + (dx + 1)];
        }
    }
    if (doGelu) acc = 0.5f * acc * (1.f + erff(acc * 0.70710678118654752f));
    out[(size_t)bc * HW + y * W + x] = acc;
}

// ---------------------------------------------------------------------------
// Pointwise (1x1-conv) SGEMM: Y[b, co, l] = sum_ci Wt[co,ci] * X[b,ci,l] (+bias)(+res)
// 128x128 tile, BK=8, 256 threads, 8x8 per thread.
// ---------------------------------------------------------------------------
__global__ __launch_bounds__(256) void gemm_pw(
    const float* __restrict__ Wt, const float* __restrict__ X,
    float* __restrict__ Y, const float* __restrict__ bias, const float* __restrict__ res,
    int M, int K, int hasBias, int hasRes)
{
    constexpr int BM = 128, BN = 128, BK = 8;
    __shared__ float As[BK][BM];
    __shared__ float Bs[BK][BN];
    int tid = threadIdx.x;
    int bn = blockIdx.x, bm = blockIdx.y, b = blockIdx.z;
    const float* Xb = X + (size_t)b * K * HW + (size_t)bn * BN;
    float acc[8][8] = {};
    int ar = tid >> 1, ac = (tid & 1) * 4;     // A tile load: 128 rows x 8 k
    int br = tid >> 5, bc = (tid & 31) * 4;    // B tile load: 8 k x 128 cols
    const float* Ap = Wt + (size_t)(bm * BM + ar) * K + ac;
    const float* Bp = Xb + (size_t)br * HW + bc;
    int ty = tid >> 4, tx = tid & 15;
    for (int k0 = 0; k0 < K; k0 += BK) {
        float4 av = *(const float4*)(Ap + k0);
        As[ac + 0][ar] = av.x; As[ac + 1][ar] = av.y;
        As[ac + 2][ar] = av.z; As[ac + 3][ar] = av.w;
        *(float4*)&Bs[br][bc] = *(const float4*)(Bp + (size_t)k0 * HW);
        __syncthreads();
        #pragma unroll
        for (int k = 0; k < BK; k++) {
            float a[8], bv[8];
            #pragma unroll
            for (int i = 0; i < 8; i++) a[i] = As[k][ty * 8 + i];
            #pragma unroll
            for (int j = 0; j < 8; j++) bv[j] = Bs[k][tx * 8 + j];
            #pragma unroll
            for (int i = 0; i < 8; i++)
                #pragma unroll
                for (int j = 0; j < 8; j++) acc[i][j] += a[i] * bv[j];
        }
        __syncthreads();
    }
    #pragma unroll
    for (int i = 0; i < 8; i++) {
        int row = bm * BM + ty * 8 + i;
        float bb = hasBias ? bias[row] : 0.f;
        #pragma unroll
        for (int j = 0; j < 8; j++) {
            int col = bn * BN + tx * 8 + j;
            size_t o = (size_t)b * M * HW + (size_t)row * HW + col;
            float v = acc[i][j] + bb;
            if (hasRes) v += res[o];
            Y[o] = v;
        }
    }
}

// ---------------------------------------------------------------------------
// Attention: per (b, h, l): a_n = SCALE * sum_d q * k ; w ∝ exp(min_a - a_n);
// out_d = sum_n w_n * v. K/V held in SMEM per batch.
// ---------------------------------------------------------------------------
__global__ void attn_kernel()
{
    __shared__ float ks[NC * C], vs[NC * C];   // 2 * 19456 B
    int b = blockIdx.y;
    int tid = threadIdx.x;
    for (int i = tid; i < NC * C; i += 256) {
        ks[i] = g_kbuf[(size_t)b * NC * C + i];
        vs[i] = g_vbuf[(size_t)b * NC * C + i];
    }
    __syncthreads();
    int h = tid >> 5, lane = tid & 31;
    int l = blockIdx.x * 32 + lane;
    const float* qp = g_qq + (size_t)b * C * HW + (size_t)(h * HD) * HW + l;
    float a[NC];
    #pragma unroll
    for (int n = 0; n < NC; n++) a[n] = 0.f;
    #pragma unroll
    for (int d = 0; d < HD; d++) {
        float qv = qp[(size_t)d * HW];
        #pragma unroll
        for (int n = 0; n < NC; n++) a[n] += qv * ks[n * C + h * HD + d];
    }
    float mn = 1e30f;
    #pragma unroll
    for (int n = 0; n < NC; n++) { a[n] *= SCALE; mn = fminf(mn, a[n]); }
    // softmax(max(a) - a) == exp(min(a) - a_n) / sum
    float s = 0.f, wgt[NC];
    #pragma unroll
    for (int n = 0; n < NC; n++) { wgt[n] = expf(mn - a[n]); s += wgt[n]; }
    float inv = 1.f / s;
    float* op = g_att + (size_t)b * C * HW + (size_t)(h * HD) * HW + l;
    #pragma unroll
    for (int d = 0; d < HD; d++) {
        float acc = 0.f;
        #pragma unroll
        for (int n = 0; n < NC; n++) acc += wgt[n] * vs[n * C + h * HD + d];
        op[(size_t)d * HW] = acc * inv;
    }
}

// ---------------------------------------------------------------------------
// Host launcher
// ---------------------------------------------------------------------------
extern "C" void kernel_launch(void* const* d_in, const int* in_sizes, int n_in,
                              void* d_out, int out_size)
{
    const float* low     = (const float*)d_in[0];
    const float* high    = (const float*)d_in[1];
    const float* gl      = (const float*)d_in[2];
    const float* bl      = (const float*)d_in[3];
    const float* gh      = (const float*)d_in[4];
    const float* bh      = (const float*)d_in[5];
    const float* gm      = (const float*)d_in[6];
    const float* bm      = (const float*)d_in[7];
    const float* w_q_dw  = (const float*)d_in[8];
    const float* b_q_dw  = (const float*)d_in[9];
    const float* w_q_pw  = (const float*)d_in[10];
    const float* b_q_pw  = (const float*)d_in[11];
    const float* w_ml1   = (const float*)d_in[12];
    const float* w_ml2   = (const float*)d_in[13];
    const float* w_align = (const float*)d_in[14];
    const float* w_kv    = (const float*)d_in[15];
    const float* b_kv    = (const float*)d_in[16];
    const float* memory  = (const float*)d_in[17];
    const float* w_proj  = (const float*)d_in[18];
    const float* b_proj  = (const float*)d_in[19];
    const float* w_mlp1  = (const float*)d_in[20];
    const float* b_mlp1  = (const float*)d_in[21];
    const float* w_mlpdw = (const float*)d_in[22];
    const float* b_mlpdw = (const float*)d_in[23];
    const float* w_mlp2  = (const float*)d_in[24];
    const float* b_mlp2  = (const float*)d_in[25];
    float* out = (float*)d_out;

    float *p_query, *p_qd, *p_qq, *p_att, *p_out, *p_y, *p_hid, *p_hid2;
    cudaGetSymbolAddress((void**)&p_query, g_query);
    cudaGetSymbolAddress((void**)&p_qd,    g_qd);
    cudaGetSymbolAddress((void**)&p_qq,    g_qq);
    cudaGetSymbolAddress((void**)&p_att,   g_att);
    cudaGetSymbolAddress((void**)&p_out,   g_outb);
    cudaGetSymbolAddress((void**)&p_y,     g_y);
    cudaGetSymbolAddress((void**)&p_hid,   g_hid);
    cudaGetSymbolAddress((void**)&p_hid2,  g_hid2);

    // 1. Dual layernorm + fuse
    ln_fuse_kernel<<<(B * HW + 255) / 256, 256>>>(low, high, gl, bl, gh, bh);

    // 2. Compose mask-path weights (ml2 @ grouped ml1)
    weff_kernel<<<NC, C>>>(w_ml2, w_ml1);

    // 3. Mask logits + aligned features (fused; dynamic smem for both weight sets)
    int smem = (NC * C + C * 64) * (int)sizeof(float);   // ~85 KB
    cudaFuncSetAttribute(mask_xa_kernel, cudaFuncAttributeMaxDynamicSharedMemorySize, smem);
    mask_xa_kernel<<<dim3(HW / 128, B), 128, smem>>>(w_align);

    // 4. Spatial softmax over HW
    softmax_hw_kernel<<<B * NC, 256>>>();

    // 5. Class prototypes cf = mask @ xa^T
    cf_kernel<<<dim3(C, B), 256>>>();

    // 6. Memory mix + kv projection
    kv_kernel<<<B * NC, 512>>>(w_kv, b_kv, memory);

    // 7. Query path: depthwise 3x3 then pointwise 1x1
    dw3x3_kernel<<<B * C * HW / 256, 256>>>(p_query, p_qd, w_q_dw, b_q_dw, C, 0);
    gemm_pw<<<dim3(HW / 128, C / 128, B), 256>>>(w_q_pw, p_qd, p_qq, b_q_pw, nullptr, C, C, 1, 0);

    // 8. Attention over NC=19 prototypes
    attn_kernel<<<dim3(HW / 32, B), 256>>>();

    // 9. Output projection + residual(low)
    gemm_pw<<<dim3(HW / 128, C / 128, B), 256>>>(w_proj, p_att, p_out, b_proj, low, C, C, 1, 1);

    // 10. FFN: LN -> 1x1 expand -> dw3x3 + GELU -> 1x1 project + residual(out)
    ln_kernel<<<(B * HW + 255) / 256, 256>>>(p_out, p_y, gm, bm);
    gemm_pw<<<dim3(HW / 128, C4 / 128, B), 256>>>(w_mlp1, p_y, p_hid, b_mlp1, nullptr, C4, C, 1, 0);
    dw3x3_kernel<<<B * C4 * HW / 256, 256>>>(p_hid, p_hid2, w_mlpdw, b_mlpdw, C4, 1);
    gemm_pw<<<dim3(HW / 128, C / 128, B), 256>>>(w_mlp2, p_hid2, out, b_mlp2, p_out, C, C4, 1, 1);
}

// round 3
// speedup vs baseline: 2.2759x; 2.2759x over previous
#include <cuda_runtime.h>
#include <cuda_bf16.h>
#include <mma.h>
#include <math.h>
#include <cstdint>

using namespace nvcuda;

// ---------------------------------------------------------------------------
// Problem constants
// ---------------------------------------------------------------------------
namespace {
constexpr int B  = 4;
constexpr int C  = 256;
constexpr int H  = 128;
constexpr int W  = 128;
constexpr int HW = H * W;          // 16384
constexpr int NC = 19;
constexpr int HD = 32;
constexpr int C4 = 4 * C;          // 1024
constexpr float SCALE = 0.17677669529663687f;
constexpr float EPS = 1e-5f;
}

// ---------------------------------------------------------------------------
// Scratch
// ---------------------------------------------------------------------------
__device__ float g_query[B * C * HW];
__device__ float g_fused[B * C * HW];
__device__ float g_mask [B * NC * HW];
__device__ float g_xa   [B * C * HW];
__device__ float g_weff [NC * C];
__device__ float g_cf   [B * NC * C];
__device__ float g_kbuf [B * NC * C];
__device__ float g_vbuf [B * NC * C];
__device__ float g_qq   [B * C * HW];
__device__ float g_outb [B * C * HW];
__device__ __nv_bfloat16 g_qdb  [B * C * HW];
__device__ __nv_bfloat16 g_attb [B * C * HW];
__device__ __nv_bfloat16 g_yb   [B * C * HW];
__device__ __nv_bfloat16 g_hidb [B * C4 * HW];
__device__ __nv_bfloat16 g_hid2b[B * C4 * HW];
__device__ __nv_bfloat16 g_wqpwb [C * C];
__device__ __nv_bfloat16 g_wprojb[C * C];
__device__ __nv_bfloat16 g_wmlp1b[C4 * C];
__device__ __nv_bfloat16 g_wmlp2b[C * C4];

// ---------------------------------------------------------------------------
// fp32 -> bf16 weight conversion
// ---------------------------------------------------------------------------
__global__ void f2bf_kernel(const float* __restrict__ in, __nv_bfloat16* __restrict__ out, int n)
{
    int i = blockIdx.x * 256 + threadIdx.x;
    if (i < n) out[i] = __float2bfloat16(in[i]);
}

// ---------------------------------------------------------------------------
// K1: LN(low) -> query ; LN(high) ; fused = 0.5*(query + ln_high)
// ---------------------------------------------------------------------------
__global__ void ln_fuse_kernel(const float* __restrict__ low, const float* __restrict__ high,
                               const float* __restrict__ gl, const float* __restrict__ bl,
                               const float* __restrict__ gh, const float* __restrict__ bh)
{
    int pos = blockIdx.x * blockDim.x + threadIdx.x;
    if (pos >= B * HW) return;
    int b = pos / HW, l = pos % HW;
    const float* lp = low  + (size_t)b * C * HW + l;
    const float* hp = high + (size_t)b * C * HW + l;
    float s1 = 0.f, s2 = 0.f, t1 = 0.f, t2 = 0.f;
    #pragma unroll 8
    for (int c = 0; c < C; c++) {
        float a = lp[(size_t)c * HW]; s1 += a; s2 += a * a;
        float e = hp[(size_t)c * HW]; t1 += e; t2 += e * e;
    }
    float mu1 = s1 * (1.f / C), mu2 = t1 * (1.f / C);
    float i1 = rsqrtf(s2 * (1.f / C) - mu1 * mu1 + EPS);
    float i2 = rsqrtf(t2 * (1.f / C) - mu2 * mu2 + EPS);
    float* qo = g_query + (size_t)b * C * HW + l;
    float* fo = g_fused + (size_t)b * C * HW + l;
    #pragma unroll 8
    for (int c = 0; c < C; c++) {
        float q = (lp[(size_t)c * HW] - mu1) * i1 * gl[c] + bl[c];
        float k = (hp[(size_t)c * HW] - mu2) * i2 * gh[c] + bh[c];
        qo[(size_t)c * HW] = q;
        fo[(size_t)c * HW] = 0.5f * (q + k);
    }
}

// LN over channels -> bf16 out
__global__ void ln_bf_kernel(const float* __restrict__ in, __nv_bfloat16* __restrict__ out,
                             const float* __restrict__ g, const float* __restrict__ bb)
{
    int pos = blockIdx.x * blockDim.x + threadIdx.x;
    if (pos >= B * HW) return;
    int b = pos / HW, l = pos % HW;
    const float* ip = in + (size_t)b * C * HW + l;
    float s1 = 0.f, s2 = 0.f;
    #pragma unroll 8
    for (int c = 0; c < C; c++) { float a = ip[(size_t)c * HW]; s1 += a; s2 += a * a; }
    float mu = s1 * (1.f / C);
    float iv = rsqrtf(s2 * (1.f / C) - mu * mu + EPS);
    __nv_bfloat16* op = out + (size_t)b * C * HW + l;
    #pragma unroll 8
    for (int c = 0; c < C; c++)
        op[(size_t)c * HW] = __float2bfloat16((ip[(size_t)c * HW] - mu) * iv * g[c] + bb[c]);
}

// ---------------------------------------------------------------------------
// K2: compose mask-path weights
// ---------------------------------------------------------------------------
__global__ void weff_kernel(const float* __restrict__ w_ml2, const float* __restrict__ w_ml1)
{
    int n = blockIdx.x, ci = threadIdx.x;
    int g = ci >> 6, jj = ci & 63;
    float acc = 0.f;
    #pragma unroll
    for (int j = 0; j < 64; j++) {
        int m = g * 64 + j;
        acc += w_ml2[n * C + m] * w_ml1[m * 64 + jj];
    }
    g_weff[n * C + ci] = acc;
}

// ---------------------------------------------------------------------------
// K3: mask logits + grouped align conv
// ---------------------------------------------------------------------------
__global__ void mask_xa_kernel(const float* __restrict__ w_align)
{
    extern __shared__ float sm[];
    float* weff_s = sm;
    float* wal_s  = sm + NC * C;
    int tid = threadIdx.x;
    for (int i = tid; i < NC * C; i += 128) weff_s[i] = g_weff[i];
    for (int i = tid; i < C * 64; i += 128) wal_s[i] = w_align[i];
    __syncthreads();
    int b = blockIdx.y;
    int l = blockIdx.x * 128 + tid;
    const float* fp = g_fused + (size_t)b * C * HW + l;
    float macc[NC];
    #pragma unroll
    for (int n = 0; n < NC; n++) macc[n] = 0.f;
    for (int g = 0; g < 4; g++) {
        float fv[64];
        #pragma unroll
        for (int j = 0; j < 64; j++) fv[j] = fp[(size_t)(g * 64 + j) * HW];
        for (int n = 0; n < NC; n++) {
            float a = 0.f;
            #pragma unroll
            for (int j = 0; j < 64; j++) a += weff_s[n * C + g * 64 + j] * fv[j];
            macc[n] += a;
        }
        for (int co = 0; co < 64; co++) {
            float a = 0.f;
            #pragma unroll
            for (int j = 0; j < 64; j++) a += wal_s[(g * 64 + co) * 64 + j] * fv[j];
            g_xa[(size_t)b * C * HW + (size_t)(g * 64 + co) * HW + l] = a;
        }
    }
    #pragma unroll
    for (int n = 0; n < NC; n++)
        g_mask[(size_t)b * NC * HW + (size_t)n * HW + l] = macc[n];
}

// ---------------------------------------------------------------------------
// K4: spatial softmax over HW per (b,nc)
// ---------------------------------------------------------------------------
__global__ void softmax_hw_kernel()
{
    __shared__ float red[256];
    int row = blockIdx.x;
    float* p = g_mask + (size_t)row * HW;
    int tid = threadIdx.x;
    float m = -1e30f;
    for (int i = tid; i < HW; i += 256) m = fmaxf(m, p[i]);
    red[tid] = m; __syncthreads();
    for (int s = 128; s > 0; s >>= 1) { if (tid < s) red[tid] = fmaxf(red[tid], red[tid + s]); __syncthreads(); }
    m = red[0]; __syncthreads();
    float s = 0.f;
    for (int i = tid; i < HW; i += 256) s += expf(p[i] - m);
    red[tid] = s; __syncthreads();
    for (int st = 128; st > 0; st >>= 1) { if (tid < st) red[tid] += red[tid + st]; __syncthreads(); }
    float inv = 1.f / red[0];
    for (int i = tid; i < HW; i += 256) p[i] = expf(p[i] - m) * inv;
}

// ---------------------------------------------------------------------------
// K5: cf[b,n,c] = sum_l mask[b,n,l] * xa[b,c,l]
// ---------------------------------------------------------------------------
__global__ void cf_kernel()
{
    int c = blockIdx.x, b = blockIdx.y;
    int tid = threadIdx.x;
    const float* xp = g_xa + (size_t)(b * C + c) * HW;
    const float* mp = g_mask + (size_t)b * NC * HW;
    float acc[NC];
    #pragma unroll
    for (int n = 0; n < NC; n++) acc[n] = 0.f;
    for (int l = tid; l < HW; l += 256) {
        float x = xp[l];
        #pragma unroll
        for (int n = 0; n < NC; n++) acc[n] += x * mp[(size_t)n * HW + l];
    }
    __shared__ float red[256];
    for (int n = 0; n < NC; n++) {
        red[tid] = acc[n]; __syncthreads();
        for (int s = 128; s > 0; s >>= 1) { if (tid < s) red[tid] += red[tid + s]; __syncthreads(); }
        if (tid == 0) g_cf[((size_t)b * NC + n) * C + c] = red[0];
        __syncthreads();
    }
}

// ---------------------------------------------------------------------------
// K6: memory-mix + kv projection
// ---------------------------------------------------------------------------
__global__ void kv_kernel(const float* __restrict__ w_kv, const float* __restrict__ b_kv,
                          const float* __restrict__ memory)
{
    int row = blockIdx.x;
    int n = row % NC;
    int tid = threadIdx.x;
    __shared__ float cfs[C];
    if (tid < C) cfs[tid] = 0.9f * g_cf[(size_t)row * C + tid] + 0.1f * memory[n * C + tid];
    __syncthreads();
    float acc = b_kv[tid];
    #pragma unroll 8
    for (int c = 0; c < C; c++) acc += cfs[c] * w_kv[(size_t)tid * C + c];
    if (tid < C) g_kbuf[(size_t)row * C + tid] = acc;
    else         g_vbuf[(size_t)row * C + tid - C] = acc;
}

// ---------------------------------------------------------------------------
// Depthwise 3x3 (+bias)(+GELU), templated IO types
// ---------------------------------------------------------------------------
__device__ __forceinline__ float ldf(const float* p) { return *p; }
__device__ __forceinline__ float ldf(const __nv_bfloat16* p) { return __bfloat162float(*p); }
__device__ __forceinline__ void stf(float* p, float v) { *p = v; }
__device__ __forceinline__ void stf(__nv_bfloat16* p, float v) { *p = __float2bfloat16(v); }

template <typename Tin, typename Tout, bool GELU>
__global__ void dw3x3_kernel(const Tin* __restrict__ in, Tout* __restrict__ out,
                             const float* __restrict__ w, const float* __restrict__ bias, int Cn)
{
    long long idx = (long long)blockIdx.x * 256 + threadIdx.x;
    int x = (int)(idx % W);
    int y = (int)((idx / W) % H);
    long long bc = idx / HW;
    int c = (int)(bc % Cn);
    const Tin* ip = in + (size_t)bc * HW;
    const float* wp = w + c * 9;
    float acc = bias[c];
    #pragma unroll
    for (int dy = -1; dy <= 1; dy++) {
        int yy = y + dy;
        if (yy < 0 || yy >= H) continue;
        #pragma unroll
        for (int dx = -1; dx <= 1; dx++) {
            int xx = x + dx;
            if (xx < 0 || xx >= W) continue;
            acc += ldf(ip + yy * W + xx) * wp[(dy + 1) * 3 + (dx + 1)];
        }
    }
    if (GELU) acc = 0.5f * acc * (1.f + erff(acc * 0.70710678118654752f));
    stf(out + (size_t)bc * HW + y * W + x, acc);
}

// ---------------------------------------------------------------------------
// Attention over NC=19 prototypes, bf16 out
// ---------------------------------------------------------------------------
__global__ void attn_kernel()
{
    __shared__ float ks[NC * C], vs[NC * C];
    int b = blockIdx.y;
    int tid = threadIdx.x;
    for (int i = tid; i < NC * C; i += 256) {
        ks[i] = g_kbuf[(size_t)b * NC * C + i];
        vs[i] = g_vbuf[(size_t)b * NC * C + i];
    }
    __syncthreads();
    int h = tid >> 5, lane = tid & 31;
    int l = blockIdx.x * 32 + lane;
    const float* qp = g_qq + (size_t)b * C * HW + (size_t)(h * HD) * HW + l;
    float a[NC];
    #pragma unroll
    for (int n = 0; n < NC; n++) a[n] = 0.f;
    #pragma unroll
    for (int d = 0; d < HD; d++) {
        float qv = qp[(size_t)d * HW];
        #pragma unroll
        for (int n = 0; n < NC; n++) a[n] += qv * ks[n * C + h * HD + d];
    }
    float mn = 1e30f;
    #pragma unroll
    for (int n = 0; n < NC; n++) { a[n] *= SCALE; mn = fminf(mn, a[n]); }
    float s = 0.f, wgt[NC];
    #pragma unroll
    for (int n = 0; n < NC; n++) { wgt[n] = expf(mn - a[n]); s += wgt[n]; }
    float inv = 1.f / s;
    __nv_bfloat16* op = g_attb + (size_t)b * C * HW + (size_t)(h * HD) * HW + l;
    #pragma unroll
    for (int d = 0; d < HD; d++) {
        float acc = 0.f;
        #pragma unroll
        for (int n = 0; n < NC; n++) acc += wgt[n] * vs[n * C + h * HD + d];
        op[(size_t)d * HW] = __float2bfloat16(acc * inv);
    }
}

// ---------------------------------------------------------------------------
// WMMA bf16 GEMM: Y[b, m, n] = sum_k W[m,k] * X[b,k,n] (+bias)(+res)
// Tile 128x128, BK=32, 256 threads (8 warps, 4x2), double-buffered SMEM.
// grid = (HW/128, M/128, B)
// ---------------------------------------------------------------------------
constexpr int LDA = 40;    // A smem leading dim (elems)
constexpr int LDB = 136;   // B smem leading dim (elems)
constexpr int LDS = 136;   // stage leading dim (f32 elems)
constexpr int A_BUF = 128 * LDA;      // elems per buffer
constexpr int B_BUF = 32 * LDB;
constexpr int GEMM_SMEM = 128 * LDS * 4;   // 69632 (stage overlays A/B buffers)

template <bool OUT_BF16, bool HAS_RES>
__global__ __launch_bounds__(256) void gemm_wmma(
    const __nv_bfloat16* __restrict__ Wb, const __nv_bfloat16* __restrict__ X,
    void* __restrict__ Y, const float* __restrict__ bias, const float* __restrict__ res,
    int M, int K)
{
    extern __shared__ char smem[];
    __nv_bfloat16* As = (__nv_bfloat16*)smem;                       // 2 * 10240 B
    __nv_bfloat16* Bs = (__nv_bfloat16*)(smem + 2 * A_BUF * 2);     // 2 * 8704 B
    float* stage = (float*)smem;                                    // overlay (epilogue)

    int tid = threadIdx.x;
    int wid = tid >> 5;
    int wm = wid >> 1;        // 0..3 -> 32-row band
    int wn = wid & 1;         // 0..1 -> 64-col band
    int n0 = blockIdx.x * 128;
    int bm = blockIdx.y;
    int b  = blockIdx.z;

    const __nv_bfloat16* Ag = Wb + (size_t)(bm * 128) * K;
    const __nv_bfloat16* Xg = X + (size_t)b * K * HW + n0;

    wmma::fragment<wmma::accumulator, 16, 16, 16, float> acc[2][4];
    #pragma unroll
    for (int i = 0; i < 2; i++)
        #pragma unroll
        for (int j = 0; j < 4; j++) wmma::fill_fragment(acc[i][j], 0.f);

    int nk = K >> 5;

    // prologue: tile 0 -> buf 0
    {
        #pragma unroll
        for (int i = 0; i < 2; i++) {
            int cid = i * 256 + tid;
            int r = cid >> 2, cg = cid & 3;
            uint4 v = *(const uint4*)(Ag + (size_t)r * K + cg * 8);
            *(uint4*)(As + r * LDA + cg * 8) = v;
        }
        #pragma unroll
        for (int i = 0; i < 2; i++) {
            int cid = i * 256 + tid;
            int r = cid >> 4, cg = cid & 15;
            uint4 v = *(const uint4*)(Xg + (size_t)r * HW + cg * 8);
            *(uint4*)(Bs + r * LDB + cg * 8) = v;
        }
    }
    __syncthreads();

    for (int kt = 0; kt < nk; kt++) {
        int buf = kt & 1;
        uint4 ra[2], rb[2];
        if (kt + 1 < nk) {
            int k0 = (kt + 1) * 32;
            #pragma unroll
            for (int i = 0; i < 2; i++) {
                int cid = i * 256 + tid;
                int r = cid >> 2, cg = cid & 3;
                ra[i] = *(const uint4*)(Ag + (size_t)r * K + k0 + cg * 8);
            }
            #pragma unroll
            for (int i = 0; i < 2; i++) {
                int cid = i * 256 + tid;
                int r = cid >> 4, cg = cid & 15;
                rb[i] = *(const uint4*)(Xg + (size_t)(k0 + r) * HW + cg * 8);
            }
        }
        const __nv_bfloat16* Ab = As + buf * A_BUF;
        const __nv_bfloat16* Bb = Bs + buf * B_BUF;
        #pragma unroll
        for (int kk = 0; kk < 2; kk++) {
            wmma::fragment<wmma::matrix_a, 16, 16, 16, __nv_bfloat16, wmma::row_major> af[2];
            wmma::fragment<wmma::matrix_b, 16, 16, 16, __nv_bfloat16, wmma::row_major> bf[4];
            #pragma unroll
            for (int i = 0; i < 2; i++)
                wmma::load_matrix_sync(af[i], Ab + (wm * 32 + i * 16) * LDA + kk * 16, LDA);
            #pragma unroll
            for (int j = 0; j < 4; j++)
                wmma::load_matrix_sync(bf[j], Bb + (kk * 16) * LDB + wn * 64 + j * 16, LDB);
            #pragma unroll
            for (int i = 0; i < 2; i++)
                #pragma unroll
                for (int j = 0; j < 4; j++)
                    wmma::mma_sync(acc[i][j], af[i], bf[j], acc[i][j]);
        }
        if (kt + 1 < nk) {
            int nb = buf ^ 1;
            #pragma unroll
            for (int i = 0; i < 2; i++) {
                int cid = i * 256 + tid;
                int r = cid >> 2, cg = cid & 3;
                *(uint4*)(As + nb * A_BUF + r * LDA + cg * 8) = ra[i];
            }
            #pragma unroll
            for (int i = 0; i < 2; i++) {
                int cid = i * 256 + tid;
                int r = cid >> 4, cg = cid & 15;
                *(uint4*)(Bs + nb * B_BUF + r * LDB + cg * 8) = rb[i];
            }
        }
        __syncthreads();
    }

    // epilogue: stage accumulators in SMEM (overlay), then fused write
    #pragma unroll
    for (int i = 0; i < 2; i++)
        #pragma unroll
        for (int j = 0; j < 4; j++)
            wmma::store_matrix_sync(stage + (wm * 32 + i * 16) * LDS + wn * 64 + j * 16,
                                    acc[i][j], LDS, wmma::mem_row_major);
    __syncthreads();

    #pragma unroll
    for (int p = 0; p < 16; p++) {
        int idx = p * 256 + tid;             // 4096 groups of 4 cols
        int r = idx >> 5, c4 = idx & 31;
        int row = bm * 128 + r;
        float bb = bias[row];
        const float* sp = stage + r * LDS + c4 * 4;
        float4 v = { sp[0] + bb, sp[1] + bb, sp[2] + bb, sp[3] + bb };
        size_t o = (size_t)b * M * HW + (size_t)row * HW + n0 + c4 * 4;
        if (HAS_RES) {
            float4 rr = *(const float4*)(res + o);
            v.x += rr.x; v.y += rr.y; v.z += rr.z; v.w += rr.w;
        }
        if (OUT_BF16) {
            __nv_bfloat162 h0 = __floats2bfloat162_rn(v.x, v.y);
            __nv_bfloat162 h1 = __floats2bfloat162_rn(v.z, v.w);
            uint2 pk = { *(uint32_t*)&h0, *(uint32_t*)&h1 };
            *(uint2*)((__nv_bfloat16*)Y + o) = pk;
        } else {
            *(float4*)((float*)Y + o) = v;
        }
    }
}

// ---------------------------------------------------------------------------
// Host launcher
// ---------------------------------------------------------------------------
extern "C" void kernel_launch(void* const* d_in, const int* in_sizes, int n_in,
                              void* d_out, int out_size)
{
    const float* low     = (const float*)d_in[0];
    const float* high    = (const float*)d_in[1];
    const float* gl      = (const float*)d_in[2];
    const float* bl      = (const float*)d_in[3];
    const float* gh      = (const float*)d_in[4];
    const float* bh      = (const float*)d_in[5];
    const float* gm      = (const float*)d_in[6];
    const float* bm      = (const float*)d_in[7];
    const float* w_q_dw  = (const float*)d_in[8];
    const float* b_q_dw  = (const float*)d_in[9];
    const float* w_q_pw  = (const float*)d_in[10];
    const float* b_q_pw  = (const float*)d_in[11];
    const float* w_ml1   = (const float*)d_in[12];
    const float* w_ml2   = (const float*)d_in[13];
    const float* w_align = (const float*)d_in[14];
    const float* w_kv    = (const float*)d_in[15];
    const float* b_kv    = (const float*)d_in[16];
    const float* memory  = (const float*)d_in[17];
    const float* w_proj  = (const float*)d_in[18];
    const float* b_proj  = (const float*)d_in[19];
    const float* w_mlp1  = (const float*)d_in[20];
    const float* b_mlp1  = (const float*)d_in[21];
    const float* w_mlpdw = (const float*)d_in[22];
    const float* b_mlpdw = (const float*)d_in[23];
    const float* w_mlp2  = (const float*)d_in[24];
    const float* b_mlp2  = (const float*)d_in[25];
    float* out = (float*)d_out;

    float *p_query, *p_qq, *p_out;
    __nv_bfloat16 *p_qdb, *p_attb, *p_yb, *p_hidb, *p_hid2b;
    __nv_bfloat16 *p_wqpwb, *p_wprojb, *p_wmlp1b, *p_wmlp2b;
    cudaGetSymbolAddress((void**)&p_query, g_query);
    cudaGetSymbolAddress((void**)&p_qq,    g_qq);
    cudaGetSymbolAddress((void**)&p_out,   g_outb);
    cudaGetSymbolAddress((void**)&p_qdb,   g_qdb);
    cudaGetSymbolAddress((void**)&p_attb,  g_attb);
    cudaGetSymbolAddress((void**)&p_yb,    g_yb);
    cudaGetSymbolAddress((void**)&p_hidb,  g_hidb);
    cudaGetSymbolAddress((void**)&p_hid2b, g_hid2b);
    cudaGetSymbolAddress((void**)&p_wqpwb,  g_wqpwb);
    cudaGetSymbolAddress((void**)&p_wprojb, g_wprojb);
    cudaGetSymbolAddress((void**)&p_wmlp1b, g_wmlp1b);
    cudaGetSymbolAddress((void**)&p_wmlp2b, g_wmlp2b);

    cudaFuncSetAttribute(gemm_wmma<false, false>, cudaFuncAttributeMaxDynamicSharedMemorySize, GEMM_SMEM);
    cudaFuncSetAttribute(gemm_wmma<false, true>,  cudaFuncAttributeMaxDynamicSharedMemorySize, GEMM_SMEM);
    cudaFuncSetAttribute(gemm_wmma<true,  false>, cudaFuncAttributeMaxDynamicSharedMemorySize, GEMM_SMEM);

    // weight conversions
    f2bf_kernel<<<(C * C + 255) / 256, 256>>>(w_q_pw, p_wqpwb, C * C);
    f2bf_kernel<<<(C * C + 255) / 256, 256>>>(w_proj, p_wprojb, C * C);
    f2bf_kernel<<<(C4 * C + 255) / 256, 256>>>(w_mlp1, p_wmlp1b, C4 * C);
    f2bf_kernel<<<(C * C4 + 255) / 256, 256>>>(w_mlp2, p_wmlp2b, C * C4);

    // 1. LN + fuse
    ln_fuse_kernel<<<(B * HW + 255) / 256, 256>>>(low, high, gl, bl, gh, bh);
    // 2-3. mask path
    weff_kernel<<<NC, C>>>(w_ml2, w_ml1);
    int smem = (NC * C + C * 64) * (int)sizeof(float);
    cudaFuncSetAttribute(mask_xa_kernel, cudaFuncAttributeMaxDynamicSharedMemorySize, smem);
    mask_xa_kernel<<<dim3(HW / 128, B), 128, smem>>>(w_align);
    // 4-6. softmax, cf, kv
    softmax_hw_kernel<<<B * NC, 256>>>();
    cf_kernel<<<dim3(C, B), 256>>>();
    kv_kernel<<<B * NC, 512>>>(w_kv, b_kv, memory);
    // 7. query depthwise, then q_pw GEMM
    dw3x3_kernel<float, __nv_bfloat16, false><<<B * C * HW / 256, 256>>>(p_query, p_qdb, w_q_dw, b_q_dw, C);
    gemm_wmma<false, false><<<dim3(HW / 128, C / 128, B), 256, GEMM_SMEM>>>(
        p_wqpwb, p_qdb, p_qq, b_q_pw, nullptr, C, C);
    // 8. attention
    attn_kernel<<<dim3(HW / 32, B), 256>>>();
    // 9. proj + residual(low)
    gemm_wmma<false, true><<<dim3(HW / 128, C / 128, B), 256, GEMM_SMEM>>>(
        p_wprojb, p_attb, p_out, b_proj, low, C, C);
    // 10. FFN
    ln_bf_kernel<<<(B * HW + 255) / 256, 256>>>(p_out, p_yb, gm, bm);
    gemm_wmma<true, false><<<dim3(HW / 128, C4 / 128, B), 256, GEMM_SMEM>>>(
        p_wmlp1b, p_yb, p_hidb, b_mlp1, nullptr, C4, C);
    dw3x3_kernel<__nv_bfloat16, __nv_bfloat16, true><<<B * C4 * HW / 256, 256>>>(
        p_hidb, p_hid2b, w_mlpdw, b_mlpdw, C4);
    gemm_wmma<false, true><<<dim3(HW / 128, C / 128, B), 256, GEMM_SMEM>>>(
        p_wmlp2b, p_hid2b, out, b_mlp2, p_out, C, C4);
}